// round 1
// baseline (speedup 1.0000x reference)
#include <cuda_runtime.h>
#include <math.h>

#define NN 100000
#define DD 128
#define TM 128

// Scratch (device globals — no allocation allowed)
__device__ __align__(16) float g_sum[(size_t)NN * DD];
__device__ __align__(16) float g_cnt[NN];
__device__ __align__(16) float g_x1[(size_t)NN * DD];

// ---------------------------------------------------------------------------
// Edge scatter: one warp per edge. Gather 512B row of x[src], vector-atomic-add
// into sum[dst], count edges per dst.
// ---------------------------------------------------------------------------
__global__ void scatter_kernel(const float* __restrict__ x,
                               const int* __restrict__ ei, int E,
                               float* __restrict__ sum, float* __restrict__ cnt)
{
    long long gt = (long long)blockIdx.x * blockDim.x + threadIdx.x;
    int e = (int)(gt >> 5);
    if (e >= E) return;
    int lane = threadIdx.x & 31;
    int src = ei[e];
    int dst = ei[E + e];
    float4 v = *(const float4*)(x + (size_t)src * DD + lane * 4);
    float* p = sum + (size_t)dst * DD + lane * 4;
    asm volatile("red.global.add.v4.f32 [%0], {%1,%2,%3,%4};"
                 :: "l"(p), "f"(v.x), "f"(v.y), "f"(v.z), "f"(v.w)
                 : "memory");
    if (lane == 0) atomicAdd(cnt + dst, 1.0f);
}

// ---------------------------------------------------------------------------
// Fused per-layer GEMM: out[i,:] = act( (sum[i,:]/max(cnt,1)) @ Wl^T
//                                       + x[i,:] @ Wr^T + b )
// Block: 128 rows x 128 cols, 256 threads, 8x8 microtile per thread.
// smem: Wt[256][128] (transposed concat of Wl,Wr) + swizzled A tile (float4).
// ---------------------------------------------------------------------------
__global__ void __launch_bounds__(256, 1) fused_kernel(
    const float* __restrict__ x,
    const float* __restrict__ sum,
    const float* __restrict__ cnt,
    const float* __restrict__ wl,
    const float* __restrict__ wr,
    const float* __restrict__ bias,
    float* __restrict__ out,
    int n_nodes, int do_gelu)
{
    extern __shared__ float smem[];
    float*  Wt  = smem;                         // 256*128 floats = 128KB
    float4* As4 = (float4*)(smem + 256 * 128);  // 128*32 float4 = 64KB (swizzled)

    const int tid = threadIdx.x;
    const int tx = tid & 15;      // n dimension (8 cols each)
    const int ty = tid >> 4;      // m dimension (8 rows each, stride 16)
    const int row0 = blockIdx.x * TM;

    // ---- Load both weight matrices transposed into smem: Wt[k][n] = W[n][k].
    // Register-transpose 4x4 blocks; coalesced-ish reads, conflict-free STS.128.
    {
        const int nb = (tid & 31) * 4;   // n block of 4
        const int kb = tid >> 5;         // 0..7
        #pragma unroll
        for (int mat = 0; mat < 2; mat++) {
            const float* W = mat ? wr : wl;
            float* WtM = Wt + mat * 128 * 128;
            #pragma unroll
            for (int it = 0; it < 4; it++) {
                int k4 = kb + 8 * it;    // float4 chunk along k: 0..31
                float4 r0 = *(const float4*)(W + (size_t)(nb + 0) * 128 + k4 * 4);
                float4 r1 = *(const float4*)(W + (size_t)(nb + 1) * 128 + k4 * 4);
                float4 r2 = *(const float4*)(W + (size_t)(nb + 2) * 128 + k4 * 4);
                float4 r3 = *(const float4*)(W + (size_t)(nb + 3) * 128 + k4 * 4);
                *(float4*)(WtM + (4 * k4 + 0) * 128 + nb) = make_float4(r0.x, r1.x, r2.x, r3.x);
                *(float4*)(WtM + (4 * k4 + 1) * 128 + nb) = make_float4(r0.y, r1.y, r2.y, r3.y);
                *(float4*)(WtM + (4 * k4 + 2) * 128 + nb) = make_float4(r0.z, r1.z, r2.z, r3.z);
                *(float4*)(WtM + (4 * k4 + 3) * 128 + nb) = make_float4(r0.w, r1.w, r2.w, r3.w);
            }
        }
    }

    float acc[8][8];
    #pragma unroll
    for (int i = 0; i < 8; i++)
        #pragma unroll
        for (int j = 0; j < 8; j++) acc[i][j] = 0.0f;

    // Two k-phases: phase 0 = aggregated neighbors (k 0..127 vs Wl),
    //               phase 1 = self features     (k 128..255 vs Wr).
    for (int ph = 0; ph < 2; ph++) {
        __syncthreads();   // also covers weight-store -> first use ordering
        {
            const int kq = tid & 31;
            #pragma unroll
            for (int it = 0; it < 16; it++) {
                int rowl = (tid + 256 * it) >> 5;   // 0..127
                int rowg = row0 + rowl;
                float4 v = make_float4(0.f, 0.f, 0.f, 0.f);
                if (rowg < n_nodes) {
                    if (ph == 0) {
                        v = *(const float4*)(sum + (size_t)rowg * DD + kq * 4);
                        float inv = 1.0f / fmaxf(cnt[rowg], 1.0f);
                        v.x *= inv; v.y *= inv; v.z *= inv; v.w *= inv;
                    } else {
                        v = *(const float4*)(x + (size_t)rowg * DD + kq * 4);
                    }
                }
                As4[rowl * 32 + (kq ^ (rowl & 31))] = v;  // XOR swizzle
            }
        }
        __syncthreads();

        const float4* Wt4 = (const float4*)(Wt + ph * 128 * 128);
        #pragma unroll 4
        for (int k = 0; k < 128; k++) {
            float4 b0 = Wt4[k * 32 + tx * 2];
            float4 b1 = Wt4[k * 32 + tx * 2 + 1];
            const int kq = k >> 2, kr = k & 3;
            float a[8];
            #pragma unroll
            for (int i = 0; i < 8; i++) {
                int m = ty + 16 * i;
                a[i] = ((const float*)&As4[m * 32 + (kq ^ (m & 31))])[kr];
            }
            #pragma unroll
            for (int i = 0; i < 8; i++) {
                acc[i][0] += a[i] * b0.x;
                acc[i][1] += a[i] * b0.y;
                acc[i][2] += a[i] * b0.z;
                acc[i][3] += a[i] * b0.w;
                acc[i][4] += a[i] * b1.x;
                acc[i][5] += a[i] * b1.y;
                acc[i][6] += a[i] * b1.z;
                acc[i][7] += a[i] * b1.w;
            }
        }
    }

    // Epilogue: bias (+ exact-erf GELU for layer 0), coalesced float4 stores.
    float bv[8];
    #pragma unroll
    for (int j = 0; j < 8; j++) bv[j] = bias[tx * 8 + j];

    #pragma unroll
    for (int i = 0; i < 8; i++) {
        int m = row0 + ty + 16 * i;
        if (m < n_nodes) {
            float o[8];
            #pragma unroll
            for (int j = 0; j < 8; j++) {
                float v = acc[i][j] + bv[j];
                if (do_gelu) v = 0.5f * v * (1.0f + erff(v * 0.70710678118654752f));
                o[j] = v;
            }
            *(float4*)(out + (size_t)m * DD + tx * 8)     = make_float4(o[0], o[1], o[2], o[3]);
            *(float4*)(out + (size_t)m * DD + tx * 8 + 4) = make_float4(o[4], o[5], o[6], o[7]);
        }
    }
}

// ---------------------------------------------------------------------------
extern "C" void kernel_launch(void* const* d_in, const int* in_sizes, int n_in,
                              void* d_out, int out_size)
{
    const float* embs = (const float*)d_in[0];
    const int*   ei0  = (const int*)d_in[1];
    const int*   ei1  = (const int*)d_in[2];
    const float* wl0  = (const float*)d_in[3];
    const float* wr0  = (const float*)d_in[4];
    const float* b0   = (const float*)d_in[5];
    const float* wl1  = (const float*)d_in[6];
    const float* wr1  = (const float*)d_in[7];
    const float* b1   = (const float*)d_in[8];
    float* out = (float*)d_out;

    const int N  = in_sizes[0] / DD;
    const int E0 = in_sizes[1] / 2;
    const int E1 = in_sizes[2] / 2;

    float *dsum, *dcnt, *dx1;
    cudaGetSymbolAddress((void**)&dsum, g_sum);
    cudaGetSymbolAddress((void**)&dcnt, g_cnt);
    cudaGetSymbolAddress((void**)&dx1,  g_x1);

    const size_t SMEM = (256 * 128 + 128 * 32 * 4) * sizeof(float);  // 192KB
    cudaFuncSetAttribute(fused_kernel,
                         cudaFuncAttributeMaxDynamicSharedMemorySize, (int)SMEM);

    const int gemm_blocks = (N + TM - 1) / TM;

    // ---- layer 0 ----
    cudaMemsetAsync(dsum, 0, (size_t)NN * DD * sizeof(float));
    cudaMemsetAsync(dcnt, 0, (size_t)NN * sizeof(float));
    {
        long long threads = (long long)E0 * 32;
        int blocks = (int)((threads + 255) / 256);
        scatter_kernel<<<blocks, 256>>>(embs, ei0, E0, dsum, dcnt);
    }
    fused_kernel<<<gemm_blocks, 256, SMEM>>>(embs, dsum, dcnt, wl0, wr0, b0,
                                             dx1, N, 1);

    // ---- layer 1 ----
    cudaMemsetAsync(dsum, 0, (size_t)NN * DD * sizeof(float));
    cudaMemsetAsync(dcnt, 0, (size_t)NN * sizeof(float));
    {
        long long threads = (long long)E1 * 32;
        int blocks = (int)((threads + 255) / 256);
        scatter_kernel<<<blocks, 256>>>(dx1, ei1, E1, dsum, dcnt);
    }
    fused_kernel<<<gemm_blocks, 256, SMEM>>>(dx1, dsum, dcnt, wl1, wr1, b1,
                                             out, N, 0);
}